// round 10
// baseline (speedup 1.0000x reference)
#include <cuda_runtime.h>
#include <cuda_bf16.h>
#include <cuda_fp16.h>
#include <math.h>
#include <cstdint>

#define Bq   128
#define Tq   256
#define Eq   512
#define Hq   1024
#define TOPq 128
#define Fq   512
#define Oq   10
#define G4   4096
#define NH   8
#define BH   (Bq * Hq)

typedef unsigned long long u64;
typedef unsigned int u32;

// ---------------- device scratch ----------------
__device__ float g_xg[(size_t)Bq * Tq * G4];
__device__ float g_tb[Bq * G4];
__device__ float g_hbuf[Bq * Hq];
__device__ __half g_h16hi[2 * BH];                 // f16(h)
__device__ __half g_h16lo[2 * BH];                 // f16((h - f16(h)) * 32)
__device__ __half g_w16[(size_t)G4 * Hq];          // f16(w_hh)
__device__ __nv_bfloat16 g_xeb[(size_t)Bq * Tq * Eq];
__device__ __nv_bfloat16 g_wihb[(size_t)G4 * Eq];
__device__ float g_h1[Bq * Fq];
__device__ float g_s[Fq];
__device__ float g_t[Fq];
__device__ unsigned int g_bar;

// ---------------- helpers ----------------
__device__ __forceinline__ float sigmoidf(float x) { return 1.0f / (1.0f + expf(-x)); }

__device__ __forceinline__ u32 smem_u32(const void* p) {
    u32 a; asm("{ .reg .u64 t; cvta.to.shared.u64 t, %1; cvt.u32.u64 %0, t; }" : "=r"(a) : "l"(p));
    return a;
}
__device__ __forceinline__ void ldm4(u32 &r0, u32 &r1, u32 &r2, u32 &r3, u32 addr) {
    asm volatile("ldmatrix.sync.aligned.m8n8.x4.shared.b16 {%0,%1,%2,%3}, [%4];"
        : "=r"(r0), "=r"(r1), "=r"(r2), "=r"(r3) : "r"(addr));
}
__device__ __forceinline__ void mma16816(float* d, const u32* a, u32 b0, u32 b1) {
    asm volatile("mma.sync.aligned.m16n8k16.row.col.f32.bf16.bf16.f32 "
        "{%0,%1,%2,%3}, {%4,%5,%6,%7}, {%8,%9}, {%0,%1,%2,%3};"
        : "+f"(d[0]), "+f"(d[1]), "+f"(d[2]), "+f"(d[3])
        : "r"(a[0]), "r"(a[1]), "r"(a[2]), "r"(a[3]), "r"(b0), "r"(b1));
}
__device__ __forceinline__ void mma16816h(float* d, const u32* a, u32 b0, u32 b1) {
    asm volatile("mma.sync.aligned.m16n8k16.row.col.f32.f16.f16.f32 "
        "{%0,%1,%2,%3}, {%4,%5,%6,%7}, {%8,%9}, {%0,%1,%2,%3};"
        : "+f"(d[0]), "+f"(d[1]), "+f"(d[2]), "+f"(d[3])
        : "r"(a[0]), "r"(a[1]), "r"(a[2]), "r"(a[3]), "r"(b0), "r"(b1));
}
__device__ __forceinline__ void cpa16(u32 dst, const void* src) {
    asm volatile("cp.async.cg.shared.global [%0], [%1], 16;" :: "r"(dst), "l"(src));
}
#define CP_COMMIT() asm volatile("cp.async.commit_group;" ::: "memory")
#define CP_WAIT0()  asm volatile("cp.async.wait_group 0;" ::: "memory")
#define CP_WAIT1()  asm volatile("cp.async.wait_group 1;" ::: "memory")

// ---------------- init ----------------
__global__ void k_init() {
    int i = blockIdx.x * blockDim.x + threadIdx.x;
    if (i == 0) g_bar = 0u;
    if (i < BH) {
        g_h16hi[i] = __float2half(0.f);
        g_h16lo[i] = __float2half(0.f);
    }
}

// ---------------- w_hh prep: f16(w) ----------------
__global__ __launch_bounds__(256) void k_wprep(const float* __restrict__ w) {
    size_t i = ((size_t)blockIdx.x * 256 + threadIdx.x) * 4;
    float4 v = *(const float4*)(w + i);
    __half a[4] = {__float2half_rn(v.x), __float2half_rn(v.y),
                   __float2half_rn(v.z), __float2half_rn(v.w)};
    *(uint2*)(g_w16 + i) = *(uint2*)a;
}

// ---------------- w_ih -> bf16 ----------------
__global__ __launch_bounds__(256) void k_wihb(const float* __restrict__ w) {
    size_t i = ((size_t)blockIdx.x * 256 + threadIdx.x) * 4;
    float4 v = *(const float4*)(w + i);
    __nv_bfloat16 b[4] = {__float2bfloat16(v.x), __float2bfloat16(v.y),
                          __float2bfloat16(v.z), __float2bfloat16(v.w)};
    *(uint2*)(g_wihb + i) = *(uint2*)b;
}

// ---------------- emb gather -> bf16 ----------------
__global__ __launch_bounds__(256) void k_xeb(const int* __restrict__ x,
                                             const float* __restrict__ emb) {
    size_t idx = (size_t)blockIdx.x * 256 + threadIdx.x;
    int m = (int)(idx >> 7);
    int e4 = ((int)idx & 127) * 4;
    int row = x[m];
    float4 v = *(const float4*)(emb + (size_t)row * Eq + e4);
    __nv_bfloat16 b[4] = {__float2bfloat16(v.x), __float2bfloat16(v.y),
                          __float2bfloat16(v.z), __float2bfloat16(v.w)};
    *(uint2*)(g_xeb + (size_t)m * Eq + e4) = *(uint2*)b;
}

// ---------------- topic bias ----------------
__global__ __launch_bounds__(256) void k_topic(const float* __restrict__ x_top,
                                               const float* __restrict__ w_th,
                                               const float* __restrict__ bias) {
    __shared__ float xt[TOPq];
    int b = blockIdx.x, tid = threadIdx.x;
    if (tid < TOPq) xt[tid] = x_top[b * TOPq + tid];
    __syncthreads();
    for (int g = tid; g < G4; g += 256) {
        const float4* wr = (const float4*)(w_th + (size_t)g * TOPq);
        float s = bias[g];
        #pragma unroll
        for (int k = 0; k < TOPq / 4; k++) {
            float4 w4 = wr[k];
            s += xt[4*k]*w4.x + xt[4*k+1]*w4.y + xt[4*k+2]*w4.z + xt[4*k+3]*w4.w;
        }
        g_tb[b * G4 + g] = s;
    }
}

// ---------------- xg GEMM (bf16 tensor, cp.async; unchanged) ----------------
#define XA_STRIDE 144
#define XA_HALF   18432
#define XB_BASE   36864
#define XB_HALF   9216
#define XG_SMEM   55296

__global__ __launch_bounds__(256) void k_xg_t() {
    extern __shared__ char dsm[];
    int tid = threadIdx.x, wid = tid >> 5, lane = tid & 31;
    int n0 = blockIdx.x * 64;
    int m0 = blockIdx.y * 128;

    int arow[4], ac[4];
    #pragma unroll
    for (int i = 0; i < 4; i++) { int u = tid + i * 256; arow[i] = u >> 3; ac[i] = u & 7; }
    int brow[2], bc[2];
    #pragma unroll
    for (int i = 0; i < 2; i++) { int u = tid + i * 256; brow[i] = u >> 3; bc[i] = u & 7; }

    u32 sb = smem_u32(dsm);
    int amrow = wid * 16 + (lane & 7) + ((lane >> 3) & 1) * 8;
    u32 aAddr = sb + amrow * XA_STRIDE + (lane >> 4) * 16;
    u32 bAddr = sb + XB_BASE + lane * XA_STRIDE;

    float acc[8][4];
    #pragma unroll
    for (int i = 0; i < 8; i++) { acc[i][0]=0.f; acc[i][1]=0.f; acc[i][2]=0.f; acc[i][3]=0.f; }

    const __nv_bfloat16* Ag = g_xeb + (size_t)m0 * Eq;
    const __nv_bfloat16* Bg = g_wihb + (size_t)n0 * Eq;

    {
        u32 aS = sb, bS = sb + XB_BASE;
        #pragma unroll
        for (int i = 0; i < 4; i++)
            cpa16(aS + arow[i] * XA_STRIDE + ac[i] * 16, Ag + (size_t)arow[i] * Eq + ac[i] * 8);
        #pragma unroll
        for (int i = 0; i < 2; i++)
            cpa16(bS + brow[i] * XA_STRIDE + bc[i] * 16, Bg + (size_t)brow[i] * Eq + bc[i] * 8);
        CP_COMMIT();
    }

    for (int c = 0; c < 8; c++) {
        int buf = c & 1;
        CP_WAIT0();
        __syncthreads();
        if (c < 7) {
            int k0 = (c + 1) * 64;
            u32 aS = sb + (buf ^ 1) * XA_HALF;
            u32 bS = sb + XB_BASE + (buf ^ 1) * XB_HALF;
            #pragma unroll
            for (int i = 0; i < 4; i++)
                cpa16(aS + arow[i] * XA_STRIDE + ac[i] * 16, Ag + (size_t)arow[i] * Eq + k0 + ac[i] * 8);
            #pragma unroll
            for (int i = 0; i < 2; i++)
                cpa16(bS + brow[i] * XA_STRIDE + bc[i] * 16, Bg + (size_t)brow[i] * Eq + k0 + bc[i] * 8);
            CP_COMMIT();
        }

        u32 oA = buf * XA_HALF, oB = buf * XB_HALF;
        #pragma unroll
        for (int s = 0; s < 4; s++) {
            u32 a[4], b0[4], b1[4], b2[4], b3[4];
            ldm4(a[0], a[1], a[2], a[3], aAddr + oA + s * 32);
            ldm4(b0[0], b0[1], b0[2], b0[3], bAddr + oB + s * 32);
            ldm4(b1[0], b1[1], b1[2], b1[3], bAddr + oB + s * 32 + 16);
            ldm4(b2[0], b2[1], b2[2], b2[3], bAddr + 4608 + oB + s * 32);
            ldm4(b3[0], b3[1], b3[2], b3[3], bAddr + 4608 + oB + s * 32 + 16);
            #pragma unroll
            for (int nt = 0; nt < 4; nt++) mma16816(acc[nt], a, b0[nt], b1[nt]);
            #pragma unroll
            for (int nt = 0; nt < 4; nt++) mma16816(acc[4 + nt], a, b2[nt], b3[nt]);
        }
    }

    int g = lane >> 2, tq = lane & 3;
    int bb = m0 >> 8;
    const float* tbr = g_tb + (size_t)bb * G4 + n0;
    #pragma unroll
    for (int rr = 0; rr < 2; rr++) {
        int m = m0 + wid * 16 + g + rr * 8;
        float* orow = g_xg + (size_t)m * G4 + n0;
        #pragma unroll
        for (int nt = 0; nt < 8; nt++) {
            int nn = nt * 8 + tq * 2;
            float2 tb2 = *(const float2*)(tbr + nn);
            float2 o;
            o.x = acc[nt][rr * 2 + 0] + tb2.x;
            o.y = acc[nt][rr * 2 + 1] + tb2.y;
            *(float2*)(orow + nn) = o;
        }
    }
}

// ---------------- persistent LSTM recurrence: per-warp pipelines ----------
// gate = accP + accL/32; K=1024 in 8 chunks of 128; warp w owns A rows
// [16w,16w+16) (copy + mma), so NO CTA sync inside the step — per-warp
// cp.async groups with 2-deep prologue, wait_group + __syncwarp only.
// Smem: A 2 bufs x (hi 34816 + lo 34816) = 139264; B 8 x 8704 = 69632 -> 208896
#define A_STRIDE 272
#define A_HILO   34816
#define A_BUFSZ  69632
#define B_BASE   139264
#define B_CHUNK  8704
#define RNN_SMEM 208896

__global__ __launch_bounds__(256) void k_rnn() {
    extern __shared__ char dsm[];
    int tid = threadIdx.x, wid = tid >> 5, lane = tid & 31;
    int n = blockIdx.x;
    u32 sb = smem_u32(dsm);

    // ---- persistent B (w16 slice): 32 rows x 1024 k ----
    {
        int brow = tid >> 3, bq = tid & 7;
        size_t grow = (size_t)((brow >> 3) * Hq + n * NH + (brow & 7)) * Hq;
        u32 d = sb + B_BASE + brow * A_STRIDE;
        #pragma unroll
        for (int c = 0; c < 8; c++) {
            cpa16(d + c * B_CHUNK + bq * 16,       g_w16 + grow + c * 128 + bq * 8);
            cpa16(d + c * B_CHUNK + (bq + 8) * 16, g_w16 + grow + c * 128 + (bq + 8) * 8);
        }
        CP_COMMIT();
    }

    // per-warp A copy mapping: lane covers row 16w+(lane>>1), 8 quads
    int acrow = wid * 16 + (lane >> 1);
    u32 aso = (u32)acrow * A_STRIDE + (lane & 1) * 128;     // smem byte offset in plane
    size_t agoff = (size_t)acrow * Hq + (lane & 1) * 64;    // gmem element offset

    int amrow = wid * 16 + (lane & 7) + ((lane >> 3) & 1) * 8;
    u32 aAddr = sb + amrow * A_STRIDE + (lane >> 4) * 16;
    u32 bAddr = sb + B_BASE + lane * A_STRIDE;

    int g = lane >> 2, tq = lane & 3;
    int u0 = tq * 2;
    float creg[4] = {0.f, 0.f, 0.f, 0.f};

    CP_WAIT0();
    __syncthreads();   // B ready

    for (int t = 0; t < Tq; t++) {
        int ph = t & 1;
        const __half* hh = g_h16hi + (size_t)ph * BH;
        const __half* hl = g_h16lo + (size_t)ph * BH;

        // ---- prefetch xg for the epilogue (independent of MMA) ----
        float2 pxg[2][4];
        #pragma unroll
        for (int rr = 0; rr < 2; rr++) {
            int b = wid * 16 + g + rr * 8;
            const float* xr = g_xg + ((size_t)b * Tq + t) * G4 + n * NH + u0;
            pxg[rr][0] = __ldcg((const float2*)(xr));
            pxg[rr][1] = __ldcg((const float2*)(xr + Hq));
            pxg[rr][2] = __ldcg((const float2*)(xr + 2 * Hq));
            pxg[rr][3] = __ldcg((const float2*)(xr + 3 * Hq));
        }

        float accP[4][4], accL[4][4];
        #pragma unroll
        for (int i = 0; i < 4; i++) {
            accP[i][0]=0.f; accP[i][1]=0.f; accP[i][2]=0.f; accP[i][3]=0.f;
            accL[i][0]=0.f; accL[i][1]=0.f; accL[i][2]=0.f; accL[i][3]=0.f;
        }

        // ---- 2-deep prologue: issue chunks 0 and 1 ----
        #pragma unroll
        for (int pc = 0; pc < 2; pc++) {
            u32 aH = sb + pc * A_BUFSZ + aso;
            u32 aL = aH + A_HILO;
            const __half* sH = hh + agoff + pc * 128;
            const __half* sL = hl + agoff + pc * 128;
            #pragma unroll
            for (int j = 0; j < 8; j++) {
                cpa16(aH + j * 16, sH + j * 8);
                cpa16(aL + j * 16, sL + j * 8);
            }
            CP_COMMIT();
        }

        #pragma unroll
        for (int c = 0; c < 8; c++) {
            int buf = c & 1;
            if (c < 7) { CP_WAIT1(); } else { CP_WAIT0(); }
            __syncwarp();

            u32 oAh = buf * A_BUFSZ;
            u32 oAl = oAh + A_HILO;
            u32 oB  = c * B_CHUNK;
            #pragma unroll
            for (int s = 0; s < 8; s++) {
                u32 ah[4], al[4], b0[4], b1[4];
                ldm4(ah[0], ah[1], ah[2], ah[3], aAddr + oAh + s * 32);
                ldm4(al[0], al[1], al[2], al[3], aAddr + oAl + s * 32);
                ldm4(b0[0], b0[1], b0[2], b0[3], bAddr + oB + s * 32);
                ldm4(b1[0], b1[1], b1[2], b1[3], bAddr + oB + s * 32 + 16);
                #pragma unroll
                for (int nt = 0; nt < 4; nt++) {
                    mma16816h(accP[nt], ah, b0[nt], b1[nt]);
                    mma16816h(accL[nt], al, b0[nt], b1[nt]);
                }
            }

            if (c < 6) {   // issue chunk c+2 into this buffer (fragments consumed)
                u32 aH = sb + buf * A_BUFSZ + aso;
                u32 aL = aH + A_HILO;
                const __half* sH = hh + agoff + (c + 2) * 128;
                const __half* sL = hl + agoff + (c + 2) * 128;
                #pragma unroll
                for (int j = 0; j < 8; j++) {
                    cpa16(aH + j * 16, sH + j * 8);
                    cpa16(aL + j * 16, sL + j * 8);
                }
                CP_COMMIT();
            }
        }

        // ---- epilogue (registers only; c persistent) ----
        int phn = (t + 1) & 1;
        const float LS = 1.0f / 32.0f;
        #pragma unroll
        for (int rr = 0; rr < 2; rr++) {
            int b = wid * 16 + g + rr * 8;

            float i0 = sigmoidf(accP[0][rr*2+0] + accL[0][rr*2+0] * LS + pxg[rr][0].x);
            float f0 = sigmoidf(accP[1][rr*2+0] + accL[1][rr*2+0] * LS + pxg[rr][1].x);
            float gg0 = tanhf(accP[2][rr*2+0] + accL[2][rr*2+0] * LS + pxg[rr][2].x);
            float o0 = sigmoidf(accP[3][rr*2+0] + accL[3][rr*2+0] * LS + pxg[rr][3].x);
            float i1 = sigmoidf(accP[0][rr*2+1] + accL[0][rr*2+1] * LS + pxg[rr][0].y);
            float f1 = sigmoidf(accP[1][rr*2+1] + accL[1][rr*2+1] * LS + pxg[rr][1].y);
            float gg1 = tanhf(accP[2][rr*2+1] + accL[2][rr*2+1] * LS + pxg[rr][2].y);
            float o1 = sigmoidf(accP[3][rr*2+1] + accL[3][rr*2+1] * LS + pxg[rr][3].y);

            float c0 = f0 * creg[rr*2+0] + i0 * gg0;
            float c1 = f1 * creg[rr*2+1] + i1 * gg1;
            creg[rr*2+0] = c0;
            creg[rr*2+1] = c1;
            float hx = o0 * tanhf(c0);
            float hy = o1 * tanhf(c1);

            size_t hob = (size_t)phn * BH + (size_t)b * Hq + n * NH + u0;
            __half hi0 = __float2half_rn(hx);
            __half hi1 = __float2half_rn(hy);
            __half lo0 = __float2half_rn((hx - __half2float(hi0)) * 32.0f);
            __half lo1 = __float2half_rn((hy - __half2float(hi1)) * 32.0f);
            __half2 hp = __halves2half2(hi0, hi1);
            __half2 lp = __halves2half2(lo0, lo1);
            __stcg((unsigned int*)(g_h16hi + hob), *(unsigned int*)&hp);
            __stcg((unsigned int*)(g_h16lo + hob), *(unsigned int*)&lp);

            if (t == Tq - 1) {
                float2 hv; hv.x = hx; hv.y = hy;
                *(float2*)(g_hbuf + (size_t)b * Hq + n * NH + u0) = hv;
            }
        }

        // ---- global barrier between steps ----
        if (t < Tq - 1) {
            __threadfence();
            __syncthreads();
            if (tid == 0) {
                atomicAdd(&g_bar, 1u);
                unsigned int tgt = 128u * (t + 1);
                volatile unsigned int* p = &g_bar;
                while (*p < tgt) { }
                __threadfence();
            }
            __syncthreads();
        }
    }
}

// ---------------- fc1 ----------------
__global__ __launch_bounds__(256) void k_fc1(const float* __restrict__ fc1_w,
                                             const float* __restrict__ fc1_b) {
    int b = blockIdx.y;
    int f = blockIdx.x * 8 + (threadIdx.x >> 5);
    int lane = threadIdx.x & 31;
    const float* hr = g_hbuf + (size_t)b * Hq;
    const float* wr = fc1_w + (size_t)f * Hq;
    float s = 0.f;
    for (int k = lane; k < Hq; k += 32) s += hr[k] * wr[k];
    #pragma unroll
    for (int off = 16; off; off >>= 1) s += __shfl_xor_sync(0xffffffffu, s, off);
    if (lane == 0) g_h1[b * Fq + f] = s + fc1_b[f];
}

// ---------------- BN stats ----------------
__global__ void k_bn(const float* __restrict__ gamma, const float* __restrict__ beta) {
    int f = threadIdx.x;
    float s = 0.f, ss = 0.f;
    for (int b = 0; b < Bq; b++) { float v = g_h1[b * Fq + f]; s += v; ss += v * v; }
    float mu = s * (1.f / Bq);
    float var = ss * (1.f / Bq) - mu * mu;
    float rstd = rsqrtf(var + 1e-5f);
    float sc = rstd * gamma[f];
    g_s[f] = sc;
    g_t[f] = beta[f] - mu * sc;
}

// ---------------- fc2 ----------------
__global__ __launch_bounds__(320) void k_out(const float* __restrict__ fc2_w,
                                             const float* __restrict__ fc2_b,
                                             float* __restrict__ out) {
    int b = blockIdx.x;
    int o = threadIdx.x >> 5;
    int lane = threadIdx.x & 31;
    const float* h1r = g_h1 + (size_t)b * Fq;
    const float* wr = fc2_w + (size_t)o * Fq;
    float s = 0.f;
    for (int f = lane; f < Fq; f += 32) s += (h1r[f] * g_s[f] + g_t[f]) * wr[f];
    #pragma unroll
    for (int off = 16; off; off >>= 1) s += __shfl_xor_sync(0xffffffffu, s, off);
    if (lane == 0) out[b * Oq + o] = s + fc2_b[o];
}

// ---------------- launch ----------------
extern "C" void kernel_launch(void* const* d_in, const int* in_sizes, int n_in,
                              void* d_out, int out_size) {
    const int*   x     = (const int*)  d_in[0];
    const float* x_top = (const float*)d_in[1];
    const float* emb   = (const float*)d_in[2];
    const float* w_ih  = (const float*)d_in[3];
    const float* w_hh  = (const float*)d_in[4];
    const float* w_th  = (const float*)d_in[5];
    const float* bias  = (const float*)d_in[6];
    const float* fc1_w = (const float*)d_in[7];
    const float* fc1_b = (const float*)d_in[8];
    const float* gamma = (const float*)d_in[9];
    const float* beta  = (const float*)d_in[10];
    const float* fc2_w = (const float*)d_in[11];
    const float* fc2_b = (const float*)d_in[12];
    float* out = (float*)d_out;

    cudaFuncSetAttribute(k_xg_t, cudaFuncAttributeMaxDynamicSharedMemorySize, XG_SMEM);
    cudaFuncSetAttribute(k_rnn,  cudaFuncAttributeMaxDynamicSharedMemorySize, RNN_SMEM);

    k_init<<<(BH + 255) / 256, 256>>>();
    k_wprep<<<(G4 * Hq / 4) / 256, 256>>>(w_hh);
    k_wihb<<<(G4 * Eq / 4) / 256, 256>>>(w_ih);
    k_xeb<<<(Bq * Tq * Eq / 4) / 256, 256>>>(x, emb);
    k_topic<<<Bq, 256>>>(x_top, w_th, bias);
    dim3 gxg(G4 / 64, (Bq * Tq) / 128);
    k_xg_t<<<gxg, 256, XG_SMEM>>>();
    k_rnn<<<128, 256, RNN_SMEM>>>();
    k_fc1<<<dim3(Fq / 8, Bq), 256>>>(fc1_w, fc1_b);
    k_bn<<<1, Fq>>>(gamma, beta);
    k_out<<<Bq, 320>>>(fc2_w, fc2_b, out);
}

// round 11
// speedup vs baseline: 1.6543x; 1.6543x over previous
#include <cuda_runtime.h>
#include <cuda_bf16.h>
#include <cuda_fp16.h>
#include <math.h>
#include <cstdint>

#define Bq   128
#define Tq   256
#define Eq   512
#define Hq   1024
#define TOPq 128
#define Fq   512
#define Oq   10
#define G4   4096
#define NH   8
#define BH   (Bq * Hq)

typedef unsigned long long u64;
typedef unsigned int u32;

// ---------------- device scratch ----------------
__device__ float g_xg[(size_t)Bq * Tq * G4];
__device__ float g_tb[Bq * G4];
__device__ float g_hbuf[Bq * Hq];
__device__ __half g_h16hi[2 * BH];                 // f16(h)
__device__ __half g_h16lo[2 * BH];                 // f16((h - f16(h)) * 32)
__device__ __half g_w16[(size_t)G4 * Hq];          // f16(w_hh)
__device__ __nv_bfloat16 g_xeb[(size_t)Bq * Tq * Eq];
__device__ __nv_bfloat16 g_wihb[(size_t)G4 * Eq];
__device__ float g_h1[Bq * Fq];
__device__ float g_s[Fq];
__device__ float g_t[Fq];
__device__ unsigned int g_bar;

// ---------------- helpers ----------------
__device__ __forceinline__ float sigmoidf(float x) { return 1.0f / (1.0f + expf(-x)); }

__device__ __forceinline__ u32 smem_u32(const void* p) {
    u32 a; asm("{ .reg .u64 t; cvta.to.shared.u64 t, %1; cvt.u32.u64 %0, t; }" : "=r"(a) : "l"(p));
    return a;
}
__device__ __forceinline__ void ldm4(u32 &r0, u32 &r1, u32 &r2, u32 &r3, u32 addr) {
    asm volatile("ldmatrix.sync.aligned.m8n8.x4.shared.b16 {%0,%1,%2,%3}, [%4];"
        : "=r"(r0), "=r"(r1), "=r"(r2), "=r"(r3) : "r"(addr));
}
__device__ __forceinline__ void mma16816(float* d, const u32* a, u32 b0, u32 b1) {
    asm volatile("mma.sync.aligned.m16n8k16.row.col.f32.bf16.bf16.f32 "
        "{%0,%1,%2,%3}, {%4,%5,%6,%7}, {%8,%9}, {%0,%1,%2,%3};"
        : "+f"(d[0]), "+f"(d[1]), "+f"(d[2]), "+f"(d[3])
        : "r"(a[0]), "r"(a[1]), "r"(a[2]), "r"(a[3]), "r"(b0), "r"(b1));
}
__device__ __forceinline__ void mma16816h(float* d, const u32* a, u32 b0, u32 b1) {
    asm volatile("mma.sync.aligned.m16n8k16.row.col.f32.f16.f16.f32 "
        "{%0,%1,%2,%3}, {%4,%5,%6,%7}, {%8,%9}, {%0,%1,%2,%3};"
        : "+f"(d[0]), "+f"(d[1]), "+f"(d[2]), "+f"(d[3])
        : "r"(a[0]), "r"(a[1]), "r"(a[2]), "r"(a[3]), "r"(b0), "r"(b1));
}
__device__ __forceinline__ void cpa16(u32 dst, const void* src) {
    asm volatile("cp.async.cg.shared.global [%0], [%1], 16;" :: "r"(dst), "l"(src));
}
#define CP_COMMIT() asm volatile("cp.async.commit_group;" ::: "memory")
#define CP_WAIT0()  asm volatile("cp.async.wait_group 0;" ::: "memory")
#define CP_WAIT1()  asm volatile("cp.async.wait_group 1;" ::: "memory")

// ---------------- init ----------------
__global__ void k_init() {
    int i = blockIdx.x * blockDim.x + threadIdx.x;
    if (i == 0) g_bar = 0u;
    if (i < BH) {
        g_h16hi[i] = __float2half(0.f);
        g_h16lo[i] = __float2half(0.f);
    }
}

// ---------------- w_hh prep: f16(w) ----------------
__global__ __launch_bounds__(256) void k_wprep(const float* __restrict__ w) {
    size_t i = ((size_t)blockIdx.x * 256 + threadIdx.x) * 4;
    float4 v = *(const float4*)(w + i);
    __half a[4] = {__float2half_rn(v.x), __float2half_rn(v.y),
                   __float2half_rn(v.z), __float2half_rn(v.w)};
    *(uint2*)(g_w16 + i) = *(uint2*)a;
}

// ---------------- w_ih -> bf16 ----------------
__global__ __launch_bounds__(256) void k_wihb(const float* __restrict__ w) {
    size_t i = ((size_t)blockIdx.x * 256 + threadIdx.x) * 4;
    float4 v = *(const float4*)(w + i);
    __nv_bfloat16 b[4] = {__float2bfloat16(v.x), __float2bfloat16(v.y),
                          __float2bfloat16(v.z), __float2bfloat16(v.w)};
    *(uint2*)(g_wihb + i) = *(uint2*)b;
}

// ---------------- emb gather -> bf16 ----------------
__global__ __launch_bounds__(256) void k_xeb(const int* __restrict__ x,
                                             const float* __restrict__ emb) {
    size_t idx = (size_t)blockIdx.x * 256 + threadIdx.x;
    int m = (int)(idx >> 7);
    int e4 = ((int)idx & 127) * 4;
    int row = x[m];
    float4 v = *(const float4*)(emb + (size_t)row * Eq + e4);
    __nv_bfloat16 b[4] = {__float2bfloat16(v.x), __float2bfloat16(v.y),
                          __float2bfloat16(v.z), __float2bfloat16(v.w)};
    *(uint2*)(g_xeb + (size_t)m * Eq + e4) = *(uint2*)b;
}

// ---------------- topic bias ----------------
__global__ __launch_bounds__(256) void k_topic(const float* __restrict__ x_top,
                                               const float* __restrict__ w_th,
                                               const float* __restrict__ bias) {
    __shared__ float xt[TOPq];
    int b = blockIdx.x, tid = threadIdx.x;
    if (tid < TOPq) xt[tid] = x_top[b * TOPq + tid];
    __syncthreads();
    for (int g = tid; g < G4; g += 256) {
        const float4* wr = (const float4*)(w_th + (size_t)g * TOPq);
        float s = bias[g];
        #pragma unroll
        for (int k = 0; k < TOPq / 4; k++) {
            float4 w4 = wr[k];
            s += xt[4*k]*w4.x + xt[4*k+1]*w4.y + xt[4*k+2]*w4.z + xt[4*k+3]*w4.w;
        }
        g_tb[b * G4 + g] = s;
    }
}

// ---------------- xg GEMM (bf16 tensor, cp.async; unchanged) ----------------
#define XA_STRIDE 144
#define XA_HALF   18432
#define XB_BASE   36864
#define XB_HALF   9216
#define XG_SMEM   55296

__global__ __launch_bounds__(256) void k_xg_t() {
    extern __shared__ char dsm[];
    int tid = threadIdx.x, wid = tid >> 5, lane = tid & 31;
    int n0 = blockIdx.x * 64;
    int m0 = blockIdx.y * 128;

    int arow[4], ac[4];
    #pragma unroll
    for (int i = 0; i < 4; i++) { int u = tid + i * 256; arow[i] = u >> 3; ac[i] = u & 7; }
    int brow[2], bc[2];
    #pragma unroll
    for (int i = 0; i < 2; i++) { int u = tid + i * 256; brow[i] = u >> 3; bc[i] = u & 7; }

    u32 sb = smem_u32(dsm);
    int amrow = wid * 16 + (lane & 7) + ((lane >> 3) & 1) * 8;
    u32 aAddr = sb + amrow * XA_STRIDE + (lane >> 4) * 16;
    u32 bAddr = sb + XB_BASE + lane * XA_STRIDE;

    float acc[8][4];
    #pragma unroll
    for (int i = 0; i < 8; i++) { acc[i][0]=0.f; acc[i][1]=0.f; acc[i][2]=0.f; acc[i][3]=0.f; }

    const __nv_bfloat16* Ag = g_xeb + (size_t)m0 * Eq;
    const __nv_bfloat16* Bg = g_wihb + (size_t)n0 * Eq;

    {
        u32 aS = sb, bS = sb + XB_BASE;
        #pragma unroll
        for (int i = 0; i < 4; i++)
            cpa16(aS + arow[i] * XA_STRIDE + ac[i] * 16, Ag + (size_t)arow[i] * Eq + ac[i] * 8);
        #pragma unroll
        for (int i = 0; i < 2; i++)
            cpa16(bS + brow[i] * XA_STRIDE + bc[i] * 16, Bg + (size_t)brow[i] * Eq + bc[i] * 8);
        CP_COMMIT();
    }

    for (int c = 0; c < 8; c++) {
        int buf = c & 1;
        CP_WAIT0();
        __syncthreads();
        if (c < 7) {
            int k0 = (c + 1) * 64;
            u32 aS = sb + (buf ^ 1) * XA_HALF;
            u32 bS = sb + XB_BASE + (buf ^ 1) * XB_HALF;
            #pragma unroll
            for (int i = 0; i < 4; i++)
                cpa16(aS + arow[i] * XA_STRIDE + ac[i] * 16, Ag + (size_t)arow[i] * Eq + k0 + ac[i] * 8);
            #pragma unroll
            for (int i = 0; i < 2; i++)
                cpa16(bS + brow[i] * XA_STRIDE + bc[i] * 16, Bg + (size_t)brow[i] * Eq + k0 + bc[i] * 8);
            CP_COMMIT();
        }

        u32 oA = buf * XA_HALF, oB = buf * XB_HALF;
        #pragma unroll
        for (int s = 0; s < 4; s++) {
            u32 a[4], b0[4], b1[4], b2[4], b3[4];
            ldm4(a[0], a[1], a[2], a[3], aAddr + oA + s * 32);
            ldm4(b0[0], b0[1], b0[2], b0[3], bAddr + oB + s * 32);
            ldm4(b1[0], b1[1], b1[2], b1[3], bAddr + oB + s * 32 + 16);
            ldm4(b2[0], b2[1], b2[2], b2[3], bAddr + 4608 + oB + s * 32);
            ldm4(b3[0], b3[1], b3[2], b3[3], bAddr + 4608 + oB + s * 32 + 16);
            #pragma unroll
            for (int nt = 0; nt < 4; nt++) mma16816(acc[nt], a, b0[nt], b1[nt]);
            #pragma unroll
            for (int nt = 0; nt < 4; nt++) mma16816(acc[4 + nt], a, b2[nt], b3[nt]);
        }
    }

    int g = lane >> 2, tq = lane & 3;
    int bb = m0 >> 8;
    const float* tbr = g_tb + (size_t)bb * G4 + n0;
    #pragma unroll
    for (int rr = 0; rr < 2; rr++) {
        int m = m0 + wid * 16 + g + rr * 8;
        float* orow = g_xg + (size_t)m * G4 + n0;
        #pragma unroll
        for (int nt = 0; nt < 8; nt++) {
            int nn = nt * 8 + tq * 2;
            float2 tb2 = *(const float2*)(tbr + nn);
            float2 o;
            o.x = acc[nt][rr * 2 + 0] + tb2.x;
            o.y = acc[nt][rr * 2 + 1] + tb2.y;
            *(float2*)(orow + nn) = o;
        }
    }
}

// ---------------- persistent LSTM recurrence: per-warp pipelines, coalesced -
// gate = accP + accL/32; K=1024 in 8 chunks of 128. Warp w owns A rows
// [16w,16w+16): coalesced copy (lanes 0-15 = one row's 16 quads = 256B
// contiguous; lanes 16-31 = next row), 2-deep cp.async pipeline, no CTA sync
// inside the step.
// Smem: A 2 bufs x (hi 34816 + lo 34816) = 139264; B 8 x 8704 = 69632 -> 208896
#define A_STRIDE 272
#define A_HILO   34816
#define A_BUFSZ  69632
#define B_BASE   139264
#define B_CHUNK  8704
#define RNN_SMEM 208896

__global__ __launch_bounds__(256) void k_rnn() {
    extern __shared__ char dsm[];
    int tid = threadIdx.x, wid = tid >> 5, lane = tid & 31;
    int n = blockIdx.x;
    u32 sb = smem_u32(dsm);

    // ---- persistent B (w16 slice): 32 rows x 1024 k ----
    {
        int brow = tid >> 3, bq = tid & 7;
        size_t grow = (size_t)((brow >> 3) * Hq + n * NH + (brow & 7)) * Hq;
        u32 d = sb + B_BASE + brow * A_STRIDE;
        #pragma unroll
        for (int c = 0; c < 8; c++) {
            cpa16(d + c * B_CHUNK + bq * 16,       g_w16 + grow + c * 128 + bq * 8);
            cpa16(d + c * B_CHUNK + (bq + 8) * 16, g_w16 + grow + c * 128 + (bq + 8) * 8);
        }
        CP_COMMIT();
    }

    // per-warp coalesced A copy: lanes 0-15 = row r quads 0-15, lanes 16-31 = row r+1
    int crow = wid * 16 + (lane >> 4);         // + i*2, i = 0..7
    int cq = lane & 15;
    u32 aso = (u32)crow * A_STRIDE + cq * 16;
    size_t agoff = (size_t)crow * Hq + cq * 8;

    int amrow = wid * 16 + (lane & 7) + ((lane >> 3) & 1) * 8;
    u32 aAddr = sb + amrow * A_STRIDE + (lane >> 4) * 16;
    u32 bAddr = sb + B_BASE + lane * A_STRIDE;

    int g = lane >> 2, tq = lane & 3;
    int u0 = tq * 2;
    float creg[4] = {0.f, 0.f, 0.f, 0.f};

    CP_WAIT0();
    __syncthreads();   // B ready

    for (int t = 0; t < Tq; t++) {
        int ph = t & 1;
        const __half* hh = g_h16hi + (size_t)ph * BH;
        const __half* hl = g_h16lo + (size_t)ph * BH;

        // ---- prefetch xg for the epilogue ----
        float2 pxg[2][4];
        #pragma unroll
        for (int rr = 0; rr < 2; rr++) {
            int b = wid * 16 + g + rr * 8;
            const float* xr = g_xg + ((size_t)b * Tq + t) * G4 + n * NH + u0;
            pxg[rr][0] = __ldcg((const float2*)(xr));
            pxg[rr][1] = __ldcg((const float2*)(xr + Hq));
            pxg[rr][2] = __ldcg((const float2*)(xr + 2 * Hq));
            pxg[rr][3] = __ldcg((const float2*)(xr + 3 * Hq));
        }

        float accP[4][4], accL[4][4];
        #pragma unroll
        for (int i = 0; i < 4; i++) {
            accP[i][0]=0.f; accP[i][1]=0.f; accP[i][2]=0.f; accP[i][3]=0.f;
            accL[i][0]=0.f; accL[i][1]=0.f; accL[i][2]=0.f; accL[i][3]=0.f;
        }

        // ---- 2-deep prologue: issue chunks 0 and 1 ----
        #pragma unroll
        for (int pc = 0; pc < 2; pc++) {
            u32 aH = sb + pc * A_BUFSZ + aso;
            u32 aL = aH + A_HILO;
            const __half* sH = hh + agoff + pc * 128;
            const __half* sL = hl + agoff + pc * 128;
            #pragma unroll
            for (int i = 0; i < 8; i++) {
                cpa16(aH + i * 2 * A_STRIDE, sH + (size_t)i * 2 * Hq);
                cpa16(aL + i * 2 * A_STRIDE, sL + (size_t)i * 2 * Hq);
            }
            CP_COMMIT();
        }

        #pragma unroll 2
        for (int c = 0; c < 8; c++) {
            int buf = c & 1;
            if (c < 7) { CP_WAIT1(); } else { CP_WAIT0(); }
            __syncwarp();

            u32 oAh = buf * A_BUFSZ;
            u32 oAl = oAh + A_HILO;
            u32 oB  = c * B_CHUNK;
            #pragma unroll
            for (int s = 0; s < 8; s++) {
                u32 ah[4], al[4], b0[4], b1[4];
                ldm4(ah[0], ah[1], ah[2], ah[3], aAddr + oAh + s * 32);
                ldm4(al[0], al[1], al[2], al[3], aAddr + oAl + s * 32);
                ldm4(b0[0], b0[1], b0[2], b0[3], bAddr + oB + s * 32);
                ldm4(b1[0], b1[1], b1[2], b1[3], bAddr + oB + s * 32 + 16);
                #pragma unroll
                for (int nt = 0; nt < 4; nt++) {
                    mma16816h(accP[nt], ah, b0[nt], b1[nt]);
                    mma16816h(accL[nt], al, b0[nt], b1[nt]);
                }
            }

            if (c < 6) {   // issue chunk c+2 into this buffer (warp-own rows)
                u32 aH = sb + buf * A_BUFSZ + aso;
                u32 aL = aH + A_HILO;
                const __half* sH = hh + agoff + (c + 2) * 128;
                const __half* sL = hl + agoff + (c + 2) * 128;
                #pragma unroll
                for (int i = 0; i < 8; i++) {
                    cpa16(aH + i * 2 * A_STRIDE, sH + (size_t)i * 2 * Hq);
                    cpa16(aL + i * 2 * A_STRIDE, sL + (size_t)i * 2 * Hq);
                }
                CP_COMMIT();
            }
        }

        // ---- epilogue (registers only; c persistent) ----
        int phn = (t + 1) & 1;
        const float LS = 1.0f / 32.0f;
        #pragma unroll
        for (int rr = 0; rr < 2; rr++) {
            int b = wid * 16 + g + rr * 8;

            float i0 = sigmoidf(accP[0][rr*2+0] + accL[0][rr*2+0] * LS + pxg[rr][0].x);
            float f0 = sigmoidf(accP[1][rr*2+0] + accL[1][rr*2+0] * LS + pxg[rr][1].x);
            float gg0 = tanhf(accP[2][rr*2+0] + accL[2][rr*2+0] * LS + pxg[rr][2].x);
            float o0 = sigmoidf(accP[3][rr*2+0] + accL[3][rr*2+0] * LS + pxg[rr][3].x);
            float i1 = sigmoidf(accP[0][rr*2+1] + accL[0][rr*2+1] * LS + pxg[rr][0].y);
            float f1 = sigmoidf(accP[1][rr*2+1] + accL[1][rr*2+1] * LS + pxg[rr][1].y);
            float gg1 = tanhf(accP[2][rr*2+1] + accL[2][rr*2+1] * LS + pxg[rr][2].y);
            float o1 = sigmoidf(accP[3][rr*2+1] + accL[3][rr*2+1] * LS + pxg[rr][3].y);

            float c0 = f0 * creg[rr*2+0] + i0 * gg0;
            float c1 = f1 * creg[rr*2+1] + i1 * gg1;
            creg[rr*2+0] = c0;
            creg[rr*2+1] = c1;
            float hx = o0 * tanhf(c0);
            float hy = o1 * tanhf(c1);

            size_t hob = (size_t)phn * BH + (size_t)b * Hq + n * NH + u0;
            __half hi0 = __float2half_rn(hx);
            __half hi1 = __float2half_rn(hy);
            __half lo0 = __float2half_rn((hx - __half2float(hi0)) * 32.0f);
            __half lo1 = __float2half_rn((hy - __half2float(hi1)) * 32.0f);
            __half2 hp = __halves2half2(hi0, hi1);
            __half2 lp = __halves2half2(lo0, lo1);
            __stcg((unsigned int*)(g_h16hi + hob), *(unsigned int*)&hp);
            __stcg((unsigned int*)(g_h16lo + hob), *(unsigned int*)&lp);

            if (t == Tq - 1) {
                float2 hv; hv.x = hx; hv.y = hy;
                *(float2*)(g_hbuf + (size_t)b * Hq + n * NH + u0) = hv;
            }
        }

        // ---- global barrier between steps ----
        if (t < Tq - 1) {
            __threadfence();
            __syncthreads();
            if (tid == 0) {
                atomicAdd(&g_bar, 1u);
                unsigned int tgt = 128u * (t + 1);
                volatile unsigned int* p = &g_bar;
                while (*p < tgt) { }
                __threadfence();
            }
            __syncthreads();
        }
    }
}

// ---------------- fc1 ----------------
__global__ __launch_bounds__(256) void k_fc1(const float* __restrict__ fc1_w,
                                             const float* __restrict__ fc1_b) {
    int b = blockIdx.y;
    int f = blockIdx.x * 8 + (threadIdx.x >> 5);
    int lane = threadIdx.x & 31;
    const float* hr = g_hbuf + (size_t)b * Hq;
    const float* wr = fc1_w + (size_t)f * Hq;
    float s = 0.f;
    for (int k = lane; k < Hq; k += 32) s += hr[k] * wr[k];
    #pragma unroll
    for (int off = 16; off; off >>= 1) s += __shfl_xor_sync(0xffffffffu, s, off);
    if (lane == 0) g_h1[b * Fq + f] = s + fc1_b[f];
}

// ---------------- BN stats ----------------
__global__ void k_bn(const float* __restrict__ gamma, const float* __restrict__ beta) {
    int f = threadIdx.x;
    float s = 0.f, ss = 0.f;
    for (int b = 0; b < Bq; b++) { float v = g_h1[b * Fq + f]; s += v; ss += v * v; }
    float mu = s * (1.f / Bq);
    float var = ss * (1.f / Bq) - mu * mu;
    float rstd = rsqrtf(var + 1e-5f);
    float sc = rstd * gamma[f];
    g_s[f] = sc;
    g_t[f] = beta[f] - mu * sc;
}

// ---------------- fc2 ----------------
__global__ __launch_bounds__(320) void k_out(const float* __restrict__ fc2_w,
                                             const float* __restrict__ fc2_b,
                                             float* __restrict__ out) {
    int b = blockIdx.x;
    int o = threadIdx.x >> 5;
    int lane = threadIdx.x & 31;
    const float* h1r = g_h1 + (size_t)b * Fq;
    const float* wr = fc2_w + (size_t)o * Fq;
    float s = 0.f;
    for (int f = lane; f < Fq; f += 32) s += (h1r[f] * g_s[f] + g_t[f]) * wr[f];
    #pragma unroll
    for (int off = 16; off; off >>= 1) s += __shfl_xor_sync(0xffffffffu, s, off);
    if (lane == 0) out[b * Oq + o] = s + fc2_b[o];
}

// ---------------- launch ----------------
extern "C" void kernel_launch(void* const* d_in, const int* in_sizes, int n_in,
                              void* d_out, int out_size) {
    const int*   x     = (const int*)  d_in[0];
    const float* x_top = (const float*)d_in[1];
    const float* emb   = (const float*)d_in[2];
    const float* w_ih  = (const float*)d_in[3];
    const float* w_hh  = (const float*)d_in[4];
    const float* w_th  = (const float*)d_in[5];
    const float* bias  = (const float*)d_in[6];
    const float* fc1_w = (const float*)d_in[7];
    const float* fc1_b = (const float*)d_in[8];
    const float* gamma = (const float*)d_in[9];
    const float* beta  = (const float*)d_in[10];
    const float* fc2_w = (const float*)d_in[11];
    const float* fc2_b = (const float*)d_in[12];
    float* out = (float*)d_out;

    cudaFuncSetAttribute(k_xg_t, cudaFuncAttributeMaxDynamicSharedMemorySize, XG_SMEM);
    cudaFuncSetAttribute(k_rnn,  cudaFuncAttributeMaxDynamicSharedMemorySize, RNN_SMEM);

    k_init<<<(BH + 255) / 256, 256>>>();
    k_wprep<<<(G4 * Hq / 4) / 256, 256>>>(w_hh);
    k_wihb<<<(G4 * Eq / 4) / 256, 256>>>(w_ih);
    k_xeb<<<(Bq * Tq * Eq / 4) / 256, 256>>>(x, emb);
    k_topic<<<Bq, 256>>>(x_top, w_th, bias);
    dim3 gxg(G4 / 64, (Bq * Tq) / 128);
    k_xg_t<<<gxg, 256, XG_SMEM>>>();
    k_rnn<<<128, 256, RNN_SMEM>>>();
    k_fc1<<<dim3(Fq / 8, Bq), 256>>>(fc1_w, fc1_b);
    k_bn<<<1, Fq>>>(gamma, beta);
    k_out<<<Bq, 320>>>(fc2_w, fc2_b, out);
}

// round 12
// speedup vs baseline: 2.4207x; 1.4633x over previous
#include <cuda_runtime.h>
#include <cuda_bf16.h>
#include <cuda_fp16.h>
#include <math.h>
#include <cstdint>

#define Bq   128
#define Tq   256
#define Eq   512
#define Hq   1024
#define TOPq 128
#define Fq   512
#define Oq   10
#define G4   4096
#define NH   8
#define BH   (Bq * Hq)

typedef unsigned long long u64;
typedef unsigned int u32;

// ---------------- device scratch ----------------
__device__ float g_xg[(size_t)Bq * Tq * G4];
__device__ float g_tb[Bq * G4];
__device__ float g_hbuf[Bq * Hq];
__device__ __half g_h16[2 * BH];                   // f16(h), double-buffered
__device__ __half g_w16[(size_t)G4 * Hq];          // f16(w_hh)
__device__ __nv_bfloat16 g_xeb[(size_t)Bq * Tq * Eq];
__device__ __nv_bfloat16 g_wihb[(size_t)G4 * Eq];
__device__ float g_h1[Bq * Fq];
__device__ float g_s[Fq];
__device__ float g_t[Fq];
__device__ unsigned int g_bar;

// ---------------- helpers ----------------
__device__ __forceinline__ float sigmoidf(float x) { return 1.0f / (1.0f + expf(-x)); }

__device__ __forceinline__ u32 smem_u32(const void* p) {
    u32 a; asm("{ .reg .u64 t; cvta.to.shared.u64 t, %1; cvt.u32.u64 %0, t; }" : "=r"(a) : "l"(p));
    return a;
}
__device__ __forceinline__ void ldm4(u32 &r0, u32 &r1, u32 &r2, u32 &r3, u32 addr) {
    asm volatile("ldmatrix.sync.aligned.m8n8.x4.shared.b16 {%0,%1,%2,%3}, [%4];"
        : "=r"(r0), "=r"(r1), "=r"(r2), "=r"(r3) : "r"(addr));
}
__device__ __forceinline__ void mma16816(float* d, const u32* a, u32 b0, u32 b1) {
    asm volatile("mma.sync.aligned.m16n8k16.row.col.f32.bf16.bf16.f32 "
        "{%0,%1,%2,%3}, {%4,%5,%6,%7}, {%8,%9}, {%0,%1,%2,%3};"
        : "+f"(d[0]), "+f"(d[1]), "+f"(d[2]), "+f"(d[3])
        : "r"(a[0]), "r"(a[1]), "r"(a[2]), "r"(a[3]), "r"(b0), "r"(b1));
}
__device__ __forceinline__ void mma16816h(float* d, const u32* a, u32 b0, u32 b1) {
    asm volatile("mma.sync.aligned.m16n8k16.row.col.f32.f16.f16.f32 "
        "{%0,%1,%2,%3}, {%4,%5,%6,%7}, {%8,%9}, {%0,%1,%2,%3};"
        : "+f"(d[0]), "+f"(d[1]), "+f"(d[2]), "+f"(d[3])
        : "r"(a[0]), "r"(a[1]), "r"(a[2]), "r"(a[3]), "r"(b0), "r"(b1));
}
__device__ __forceinline__ void cpa16(u32 dst, const void* src) {
    asm volatile("cp.async.cg.shared.global [%0], [%1], 16;" :: "r"(dst), "l"(src));
}
#define CP_COMMIT() asm volatile("cp.async.commit_group;" ::: "memory")
#define CP_WAIT0()  asm volatile("cp.async.wait_group 0;" ::: "memory")
#define CP_WAIT1()  asm volatile("cp.async.wait_group 1;" ::: "memory")

// ---------------- init ----------------
__global__ void k_init() {
    int i = blockIdx.x * blockDim.x + threadIdx.x;
    if (i == 0) g_bar = 0u;
    if (i < BH) g_h16[i] = __float2half(0.f);
}

// ---------------- w_hh prep: f16(w) ----------------
__global__ __launch_bounds__(256) void k_wprep(const float* __restrict__ w) {
    size_t i = ((size_t)blockIdx.x * 256 + threadIdx.x) * 4;
    float4 v = *(const float4*)(w + i);
    __half a[4] = {__float2half_rn(v.x), __float2half_rn(v.y),
                   __float2half_rn(v.z), __float2half_rn(v.w)};
    *(uint2*)(g_w16 + i) = *(uint2*)a;
}

// ---------------- w_ih -> bf16 ----------------
__global__ __launch_bounds__(256) void k_wihb(const float* __restrict__ w) {
    size_t i = ((size_t)blockIdx.x * 256 + threadIdx.x) * 4;
    float4 v = *(const float4*)(w + i);
    __nv_bfloat16 b[4] = {__float2bfloat16(v.x), __float2bfloat16(v.y),
                          __float2bfloat16(v.z), __float2bfloat16(v.w)};
    *(uint2*)(g_wihb + i) = *(uint2*)b;
}

// ---------------- emb gather -> bf16 ----------------
__global__ __launch_bounds__(256) void k_xeb(const int* __restrict__ x,
                                             const float* __restrict__ emb) {
    size_t idx = (size_t)blockIdx.x * 256 + threadIdx.x;
    int m = (int)(idx >> 7);
    int e4 = ((int)idx & 127) * 4;
    int row = x[m];
    float4 v = *(const float4*)(emb + (size_t)row * Eq + e4);
    __nv_bfloat16 b[4] = {__float2bfloat16(v.x), __float2bfloat16(v.y),
                          __float2bfloat16(v.z), __float2bfloat16(v.w)};
    *(uint2*)(g_xeb + (size_t)m * Eq + e4) = *(uint2*)b;
}

// ---------------- topic bias ----------------
__global__ __launch_bounds__(256) void k_topic(const float* __restrict__ x_top,
                                               const float* __restrict__ w_th,
                                               const float* __restrict__ bias) {
    __shared__ float xt[TOPq];
    int b = blockIdx.x, tid = threadIdx.x;
    if (tid < TOPq) xt[tid] = x_top[b * TOPq + tid];
    __syncthreads();
    for (int g = tid; g < G4; g += 256) {
        const float4* wr = (const float4*)(w_th + (size_t)g * TOPq);
        float s = bias[g];
        #pragma unroll
        for (int k = 0; k < TOPq / 4; k++) {
            float4 w4 = wr[k];
            s += xt[4*k]*w4.x + xt[4*k+1]*w4.y + xt[4*k+2]*w4.z + xt[4*k+3]*w4.w;
        }
        g_tb[b * G4 + g] = s;
    }
}

// ---------------- xg GEMM (bf16 tensor, cp.async; unchanged) ----------------
#define XA_STRIDE 144
#define XA_HALF   18432
#define XB_BASE   36864
#define XB_HALF   9216
#define XG_SMEM   55296

__global__ __launch_bounds__(256) void k_xg_t() {
    extern __shared__ char dsm[];
    int tid = threadIdx.x, wid = tid >> 5, lane = tid & 31;
    int n0 = blockIdx.x * 64;
    int m0 = blockIdx.y * 128;

    int arow[4], ac[4];
    #pragma unroll
    for (int i = 0; i < 4; i++) { int u = tid + i * 256; arow[i] = u >> 3; ac[i] = u & 7; }
    int brow[2], bc[2];
    #pragma unroll
    for (int i = 0; i < 2; i++) { int u = tid + i * 256; brow[i] = u >> 3; bc[i] = u & 7; }

    u32 sb = smem_u32(dsm);
    int amrow = wid * 16 + (lane & 7) + ((lane >> 3) & 1) * 8;
    u32 aAddr = sb + amrow * XA_STRIDE + (lane >> 4) * 16;
    u32 bAddr = sb + XB_BASE + lane * XA_STRIDE;

    float acc[8][4];
    #pragma unroll
    for (int i = 0; i < 8; i++) { acc[i][0]=0.f; acc[i][1]=0.f; acc[i][2]=0.f; acc[i][3]=0.f; }

    const __nv_bfloat16* Ag = g_xeb + (size_t)m0 * Eq;
    const __nv_bfloat16* Bg = g_wihb + (size_t)n0 * Eq;

    {
        u32 aS = sb, bS = sb + XB_BASE;
        #pragma unroll
        for (int i = 0; i < 4; i++)
            cpa16(aS + arow[i] * XA_STRIDE + ac[i] * 16, Ag + (size_t)arow[i] * Eq + ac[i] * 8);
        #pragma unroll
        for (int i = 0; i < 2; i++)
            cpa16(bS + brow[i] * XA_STRIDE + bc[i] * 16, Bg + (size_t)brow[i] * Eq + bc[i] * 8);
        CP_COMMIT();
    }

    for (int c = 0; c < 8; c++) {
        int buf = c & 1;
        CP_WAIT0();
        __syncthreads();
        if (c < 7) {
            int k0 = (c + 1) * 64;
            u32 aS = sb + (buf ^ 1) * XA_HALF;
            u32 bS = sb + XB_BASE + (buf ^ 1) * XB_HALF;
            #pragma unroll
            for (int i = 0; i < 4; i++)
                cpa16(aS + arow[i] * XA_STRIDE + ac[i] * 16, Ag + (size_t)arow[i] * Eq + k0 + ac[i] * 8);
            #pragma unroll
            for (int i = 0; i < 2; i++)
                cpa16(bS + brow[i] * XA_STRIDE + bc[i] * 16, Bg + (size_t)brow[i] * Eq + k0 + bc[i] * 8);
            CP_COMMIT();
        }

        u32 oA = buf * XA_HALF, oB = buf * XB_HALF;
        #pragma unroll
        for (int s = 0; s < 4; s++) {
            u32 a[4], b0[4], b1[4], b2[4], b3[4];
            ldm4(a[0], a[1], a[2], a[3], aAddr + oA + s * 32);
            ldm4(b0[0], b0[1], b0[2], b0[3], bAddr + oB + s * 32);
            ldm4(b1[0], b1[1], b1[2], b1[3], bAddr + oB + s * 32 + 16);
            ldm4(b2[0], b2[1], b2[2], b2[3], bAddr + 4608 + oB + s * 32);
            ldm4(b3[0], b3[1], b3[2], b3[3], bAddr + 4608 + oB + s * 32 + 16);
            #pragma unroll
            for (int nt = 0; nt < 4; nt++) mma16816(acc[nt], a, b0[nt], b1[nt]);
            #pragma unroll
            for (int nt = 0; nt < 4; nt++) mma16816(acc[4 + nt], a, b2[nt], b3[nt]);
        }
    }

    int g = lane >> 2, tq = lane & 3;
    int bb = m0 >> 8;
    const float* tbr = g_tb + (size_t)bb * G4 + n0;
    #pragma unroll
    for (int rr = 0; rr < 2; rr++) {
        int m = m0 + wid * 16 + g + rr * 8;
        float* orow = g_xg + (size_t)m * G4 + n0;
        #pragma unroll
        for (int nt = 0; nt < 8; nt++) {
            int nn = nt * 8 + tq * 2;
            float2 tb2 = *(const float2*)(tbr + nn);
            float2 o;
            o.x = acc[nt][rr * 2 + 0] + tb2.x;
            o.y = acc[nt][rr * 2 + 1] + tb2.y;
            *(float2*)(orow + nn) = o;
        }
    }
}

// ---------------- persistent LSTM recurrence: single-pass fp16 -------------
// gate = f16(h)·f16(w); K=1024 in 8 chunks of 128. Warp w owns A rows
// [16w,16w+16): coalesced copy, 2-deep cp.async pipeline, no CTA sync in step.
// Smem: A 2 bufs x 34816 = 69632; B 8 x 8704 = 69632 -> 139264
#define A_STRIDE 272
#define A_BUFSZ  34816
#define B_BASE   69632
#define B_CHUNK  8704
#define RNN_SMEM 139264

__global__ __launch_bounds__(256) void k_rnn() {
    extern __shared__ char dsm[];
    int tid = threadIdx.x, wid = tid >> 5, lane = tid & 31;
    int n = blockIdx.x;
    u32 sb = smem_u32(dsm);

    // ---- persistent B (w16 slice): 32 rows x 1024 k ----
    {
        int brow = tid >> 3, bq = tid & 7;
        size_t grow = (size_t)((brow >> 3) * Hq + n * NH + (brow & 7)) * Hq;
        u32 d = sb + B_BASE + brow * A_STRIDE;
        #pragma unroll
        for (int c = 0; c < 8; c++) {
            cpa16(d + c * B_CHUNK + bq * 16,       g_w16 + grow + c * 128 + bq * 8);
            cpa16(d + c * B_CHUNK + (bq + 8) * 16, g_w16 + grow + c * 128 + (bq + 8) * 8);
        }
        CP_COMMIT();
    }

    // per-warp coalesced A copy: lanes 0-15 = row r quads 0-15, lanes 16-31 = row r+1
    int crow = wid * 16 + (lane >> 4);
    int cq = lane & 15;
    u32 aso = (u32)crow * A_STRIDE + cq * 16;
    size_t agoff = (size_t)crow * Hq + cq * 8;

    int amrow = wid * 16 + (lane & 7) + ((lane >> 3) & 1) * 8;
    u32 aAddr = sb + amrow * A_STRIDE + (lane >> 4) * 16;
    u32 bAddr = sb + B_BASE + lane * A_STRIDE;

    int g = lane >> 2, tq = lane & 3;
    int u0 = tq * 2;
    float creg[4] = {0.f, 0.f, 0.f, 0.f};

    CP_WAIT0();
    __syncthreads();   // B ready

    for (int t = 0; t < Tq; t++) {
        int ph = t & 1;
        const __half* hh = g_h16 + (size_t)ph * BH;

        // ---- prefetch xg for the epilogue ----
        float2 pxg[2][4];
        #pragma unroll
        for (int rr = 0; rr < 2; rr++) {
            int b = wid * 16 + g + rr * 8;
            const float* xr = g_xg + ((size_t)b * Tq + t) * G4 + n * NH + u0;
            pxg[rr][0] = __ldcg((const float2*)(xr));
            pxg[rr][1] = __ldcg((const float2*)(xr + Hq));
            pxg[rr][2] = __ldcg((const float2*)(xr + 2 * Hq));
            pxg[rr][3] = __ldcg((const float2*)(xr + 3 * Hq));
        }

        float acc[4][4];
        #pragma unroll
        for (int i = 0; i < 4; i++) { acc[i][0]=0.f; acc[i][1]=0.f; acc[i][2]=0.f; acc[i][3]=0.f; }

        // ---- 2-deep prologue: issue chunks 0 and 1 ----
        #pragma unroll
        for (int pc = 0; pc < 2; pc++) {
            u32 aH = sb + pc * A_BUFSZ + aso;
            const __half* sH = hh + agoff + pc * 128;
            #pragma unroll
            for (int i = 0; i < 8; i++)
                cpa16(aH + i * 2 * A_STRIDE, sH + (size_t)i * 2 * Hq);
            CP_COMMIT();
        }

        #pragma unroll 2
        for (int c = 0; c < 8; c++) {
            int buf = c & 1;
            if (c < 7) { CP_WAIT1(); } else { CP_WAIT0(); }
            __syncwarp();

            u32 oAh = buf * A_BUFSZ;
            u32 oB  = c * B_CHUNK;
            #pragma unroll
            for (int s = 0; s < 8; s++) {
                u32 ah[4], b0[4], b1[4];
                ldm4(ah[0], ah[1], ah[2], ah[3], aAddr + oAh + s * 32);
                ldm4(b0[0], b0[1], b0[2], b0[3], bAddr + oB + s * 32);
                ldm4(b1[0], b1[1], b1[2], b1[3], bAddr + oB + s * 32 + 16);
                #pragma unroll
                for (int nt = 0; nt < 4; nt++)
                    mma16816h(acc[nt], ah, b0[nt], b1[nt]);
            }

            if (c < 6) {   // issue chunk c+2 into this buffer (warp-own rows)
                u32 aH = sb + buf * A_BUFSZ + aso;
                const __half* sH = hh + agoff + (c + 2) * 128;
                #pragma unroll
                for (int i = 0; i < 8; i++)
                    cpa16(aH + i * 2 * A_STRIDE, sH + (size_t)i * 2 * Hq);
                CP_COMMIT();
            }
        }

        // ---- epilogue (registers only; c persistent) ----
        int phn = (t + 1) & 1;
        #pragma unroll
        for (int rr = 0; rr < 2; rr++) {
            int b = wid * 16 + g + rr * 8;

            float i0 = sigmoidf(acc[0][rr*2+0] + pxg[rr][0].x);
            float f0 = sigmoidf(acc[1][rr*2+0] + pxg[rr][1].x);
            float gg0 = tanhf(acc[2][rr*2+0] + pxg[rr][2].x);
            float o0 = sigmoidf(acc[3][rr*2+0] + pxg[rr][3].x);
            float i1 = sigmoidf(acc[0][rr*2+1] + pxg[rr][0].y);
            float f1 = sigmoidf(acc[1][rr*2+1] + pxg[rr][1].y);
            float gg1 = tanhf(acc[2][rr*2+1] + pxg[rr][2].y);
            float o1 = sigmoidf(acc[3][rr*2+1] + pxg[rr][3].y);

            float c0 = f0 * creg[rr*2+0] + i0 * gg0;
            float c1 = f1 * creg[rr*2+1] + i1 * gg1;
            creg[rr*2+0] = c0;
            creg[rr*2+1] = c1;
            float hx = o0 * tanhf(c0);
            float hy = o1 * tanhf(c1);

            size_t hob = (size_t)phn * BH + (size_t)b * Hq + n * NH + u0;
            __half2 hp = __halves2half2(__float2half_rn(hx), __float2half_rn(hy));
            __stcg((unsigned int*)(g_h16 + hob), *(unsigned int*)&hp);

            if (t == Tq - 1) {
                float2 hv; hv.x = hx; hv.y = hy;
                *(float2*)(g_hbuf + (size_t)b * Hq + n * NH + u0) = hv;
            }
        }

        // ---- global barrier between steps ----
        if (t < Tq - 1) {
            __threadfence();
            __syncthreads();
            if (tid == 0) {
                atomicAdd(&g_bar, 1u);
                unsigned int tgt = 128u * (t + 1);
                volatile unsigned int* p = &g_bar;
                while (*p < tgt) { }
                __threadfence();
            }
            __syncthreads();
        }
    }
}

// ---------------- fc1 ----------------
__global__ __launch_bounds__(256) void k_fc1(const float* __restrict__ fc1_w,
                                             const float* __restrict__ fc1_b) {
    int b = blockIdx.y;
    int f = blockIdx.x * 8 + (threadIdx.x >> 5);
    int lane = threadIdx.x & 31;
    const float* hr = g_hbuf + (size_t)b * Hq;
    const float* wr = fc1_w + (size_t)f * Hq;
    float s = 0.f;
    for (int k = lane; k < Hq; k += 32) s += hr[k] * wr[k];
    #pragma unroll
    for (int off = 16; off; off >>= 1) s += __shfl_xor_sync(0xffffffffu, s, off);
    if (lane == 0) g_h1[b * Fq + f] = s + fc1_b[f];
}

// ---------------- BN stats ----------------
__global__ void k_bn(const float* __restrict__ gamma, const float* __restrict__ beta) {
    int f = threadIdx.x;
    float s = 0.f, ss = 0.f;
    for (int b = 0; b < Bq; b++) { float v = g_h1[b * Fq + f]; s += v; ss += v * v; }
    float mu = s * (1.f / Bq);
    float var = ss * (1.f / Bq) - mu * mu;
    float rstd = rsqrtf(var + 1e-5f);
    float sc = rstd * gamma[f];
    g_s[f] = sc;
    g_t[f] = beta[f] - mu * sc;
}

// ---------------- fc2 ----------------
__global__ __launch_bounds__(320) void k_out(const float* __restrict__ fc2_w,
                                             const float* __restrict__ fc2_b,
                                             float* __restrict__ out) {
    int b = blockIdx.x;
    int o = threadIdx.x >> 5;
    int lane = threadIdx.x & 31;
    const float* h1r = g_h1 + (size_t)b * Fq;
    const float* wr = fc2_w + (size_t)o * Fq;
    float s = 0.f;
    for (int f = lane; f < Fq; f += 32) s += (h1r[f] * g_s[f] + g_t[f]) * wr[f];
    #pragma unroll
    for (int off = 16; off; off >>= 1) s += __shfl_xor_sync(0xffffffffu, s, off);
    if (lane == 0) out[b * Oq + o] = s + fc2_b[o];
}

// ---------------- launch ----------------
extern "C" void kernel_launch(void* const* d_in, const int* in_sizes, int n_in,
                              void* d_out, int out_size) {
    const int*   x     = (const int*)  d_in[0];
    const float* x_top = (const float*)d_in[1];
    const float* emb   = (const float*)d_in[2];
    const float* w_ih  = (const float*)d_in[3];
    const float* w_hh  = (const float*)d_in[4];
    const float* w_th  = (const float*)d_in[5];
    const float* bias  = (const float*)d_in[6];
    const float* fc1_w = (const float*)d_in[7];
    const float* fc1_b = (const float*)d_in[8];
    const float* gamma = (const float*)d_in[9];
    const float* beta  = (const float*)d_in[10];
    const float* fc2_w = (const float*)d_in[11];
    const float* fc2_b = (const float*)d_in[12];
    float* out = (float*)d_out;

    cudaFuncSetAttribute(k_xg_t, cudaFuncAttributeMaxDynamicSharedMemorySize, XG_SMEM);
    cudaFuncSetAttribute(k_rnn,  cudaFuncAttributeMaxDynamicSharedMemorySize, RNN_SMEM);

    k_init<<<(BH + 255) / 256, 256>>>();
    k_wprep<<<(G4 * Hq / 4) / 256, 256>>>(w_hh);
    k_wihb<<<(G4 * Eq / 4) / 256, 256>>>(w_ih);
    k_xeb<<<(Bq * Tq * Eq / 4) / 256, 256>>>(x, emb);
    k_topic<<<Bq, 256>>>(x_top, w_th, bias);
    dim3 gxg(G4 / 64, (Bq * Tq) / 128);
    k_xg_t<<<gxg, 256, XG_SMEM>>>();
    k_rnn<<<128, 256, RNN_SMEM>>>();
    k_fc1<<<dim3(Fq / 8, Bq), 256>>>(fc1_w, fc1_b);
    k_bn<<<1, Fq>>>(gamma, beta);
    k_out<<<Bq, 320>>>(fc2_w, fc2_b, out);
}